// round 4
// baseline (speedup 1.0000x reference)
#include <cuda_runtime.h>
#include <cuda_bf16.h>

// OccupancyGridForestAS: 4.19M points, 8x8x8 block lookup -> 64 trees of 64^3 voxels.
//
// inputs (metadata order):
//   d_in[0]: pts            float32 [N_PTS, 3]
//   d_in[1]: occ_val_grid   float32 [64, 64, 64, 64]
//   d_in[2]: block_lookup   int32   [8, 8, 8]
// output: float32 [N_PTS]
//
// R4: persistent grid-stride kernel (1184 blocks = 148 SMs x 8 resident),
// software-pipelined: next iteration's 3 streaming float2 loads are issued
// BEFORE the current iteration's compute/gather/store, overlapping stream
// latency with gather latency. No wave tail.

#define RES   64
#define LDIM  8

__global__ void __launch_bounds__(256)
occ_forest_kernel(const float2* __restrict__ pts2,
                  const float*  __restrict__ occ,
                  const int*    __restrict__ lut,
                  float2*       __restrict__ out2,
                  int n2)
{
    const int stride = gridDim.x * blockDim.x;
    int t = blockIdx.x * blockDim.x + threadIdx.x;
    if (t >= n2) return;

    // Prologue: load first chunk (2 points = 3 float2, coalesced)
    float2 v0 = __ldcs(&pts2[3 * t + 0]);
    float2 v1 = __ldcs(&pts2[3 * t + 1]);
    float2 v2 = __ldcs(&pts2[3 * t + 2]);

    while (true) {
        // Issue next chunk's streaming loads before touching current data
        int tn = t + stride;
        bool has_next = tn < n2;
        float2 w0, w1, w2;
        if (has_next) {
            w0 = __ldcs(&pts2[3 * tn + 0]);
            w1 = __ldcs(&pts2[3 * tn + 1]);
            w2 = __ldcs(&pts2[3 * tn + 2]);
        }

        // ---- process current chunk ----
        float px[2] = {v0.x, v1.y};
        float py[2] = {v0.y, v2.x};
        float pz[2] = {v1.x, v2.y};

        int  idx[2];
        bool valid[2];

#pragma unroll
        for (int i = 0; i < 2; i++) {
            float x = px[i], y = py[i], z = pz[i];

            int bx = (int)floorf(x);
            int by = (int)floorf(y);
            int bz = (int)floorf(z);

            bool in_dom = (bx >= 0) & (bx < LDIM) &
                          (by >= 0) & (by < LDIM) &
                          (bz >= 0) & (bz < LDIM);

            int cx = min(max(bx, 0), LDIM - 1);
            int cy = min(max(by, 0), LDIM - 1);
            int cz = min(max(bz, 0), LDIM - 1);

            int bidx = __ldg(&lut[cx * (LDIM * LDIM) + cy * LDIM + cz]);
            valid[i] = in_dom && (bidx >= 0);

            // Match reference float sequence exactly:
            //   block_x = 2*(p - bcs) - 1 ; vox = clip(floor((bx*0.5+0.5)*RES), 0, RES-1)
            float bxf = 2.0f * (x - (float)cx) - 1.0f;
            float byf = 2.0f * (y - (float)cy) - 1.0f;
            float bzf = 2.0f * (z - (float)cz) - 1.0f;

            int vx = min(max((int)floorf((bxf * 0.5f + 0.5f) * (float)RES), 0), RES - 1);
            int vy = min(max((int)floorf((byf * 0.5f + 0.5f) * (float)RES), 0), RES - 1);
            int vz = min(max((int)floorf((bzf * 0.5f + 0.5f) * (float)RES), 0), RES - 1);

            idx[i] = bidx * (RES * RES * RES) + vx * (RES * RES) + vy * RES + vz;
        }

        float r0 = valid[0] ? __ldg(&occ[idx[0]]) : 0.0f;
        float r1 = valid[1] ? __ldg(&occ[idx[1]]) : 0.0f;

        float2 o; o.x = r0; o.y = r1;
        __stcs(&out2[t], o);
        // ---- end current chunk ----

        if (!has_next) break;
        v0 = w0; v1 = w1; v2 = w2;
        t = tn;
    }
}

extern "C" void kernel_launch(void* const* d_in, const int* in_sizes, int n_in,
                              void* d_out, int out_size)
{
    const float2* pts2 = (const float2*)d_in[0];
    const float*  occ  = (const float*)d_in[1];
    const int*    lut  = (const int*)d_in[2];
    float2*       out  = (float2*)d_out;

    int n_pts = in_sizes[0] / 3;       // 4,194,304
    int n2    = n_pts / 2;             // 2,097,152

    int threads = 256;
    int blocks  = 148 * 8;             // persistent: one full resident wave
    occ_forest_kernel<<<blocks, threads>>>(pts2, occ, lut, out, n2);
}

// round 5
// speedup vs baseline: 1.0987x; 1.0987x over previous
#include <cuda_runtime.h>
#include <cuda_bf16.h>

// OccupancyGridForestAS: 4.19M points, 8x8x8 block lookup -> 64 trees of 64^3 voxels.
//
// inputs (metadata order):
//   d_in[0]: pts            float32 [N_PTS, 3]
//   d_in[1]: occ_val_grid   float32 [64, 64, 64, 64]
//   d_in[2]: block_lookup   int32   [8, 8, 8]
// output: float32 [N_PTS]
//
// R5: back to R3 shape (2 pts/thread, 8192 blocks, 6.92 waves) plus:
//  - block_lookup in shared memory (removes 1 LDG per point, off LSU)
//  - redundant vox clamps dropped (valid points provably in [0,63])
//  - __ldcg for the random grid gather (L1 bypass; ~0% L1 hit anyway)

#define RES   64
#define LDIM  8

__global__ void __launch_bounds__(256)
occ_forest_kernel(const float2* __restrict__ pts2,
                  const float*  __restrict__ occ,
                  const int*    __restrict__ lut,
                  float2*       __restrict__ out2,
                  int n2)
{
    __shared__ int s_lut[LDIM * LDIM * LDIM];   // 512 ints = 2KB

    // Cooperative lut fill (256 threads x 2)
    {
        int tid = threadIdx.x;
        s_lut[tid]       = lut[tid];
        s_lut[tid + 256] = lut[tid + 256];
    }
    __syncthreads();

    int t = blockIdx.x * blockDim.x + threadIdx.x;
    if (t >= n2) return;

    // 2 points = 6 floats = 3 float2 (coalesced, evict-first in L2)
    float2 v0 = __ldcs(&pts2[3 * t + 0]);
    float2 v1 = __ldcs(&pts2[3 * t + 1]);
    float2 v2 = __ldcs(&pts2[3 * t + 2]);

    float px[2] = {v0.x, v1.y};
    float py[2] = {v0.y, v2.x};
    float pz[2] = {v1.x, v2.y};

    int  idx[2];
    bool valid[2];

    // Phase 1: index math for both points (no cross-point dependencies)
#pragma unroll
    for (int i = 0; i < 2; i++) {
        float x = px[i], y = py[i], z = pz[i];

        int bx = (int)floorf(x);
        int by = (int)floorf(y);
        int bz = (int)floorf(z);

        bool in_dom = (bx >= 0) & (bx < LDIM) &
                      (by >= 0) & (by < LDIM) &
                      (bz >= 0) & (bz < LDIM);

        int cx = min(max(bx, 0), LDIM - 1);
        int cy = min(max(by, 0), LDIM - 1);
        int cz = min(max(bz, 0), LDIM - 1);

        int bidx = s_lut[cx * (LDIM * LDIM) + cy * LDIM + cz];
        valid[i] = in_dom && (bidx >= 0);

        // Bit-exact reference float sequence:
        //   block_x = 2*(p - bcs) - 1 ; vox = floor((block_x*0.5 + 0.5) * RES)
        // For valid points x-cx in [0,1) => vox provably in [0,63]; no clamps
        // needed (invalid points never issue the load, garbage idx is fine).
        float bxf = 2.0f * (x - (float)cx) - 1.0f;
        float byf = 2.0f * (y - (float)cy) - 1.0f;
        float bzf = 2.0f * (z - (float)cz) - 1.0f;

        int vx = (int)floorf((bxf * 0.5f + 0.5f) * (float)RES);
        int vy = (int)floorf((byf * 0.5f + 0.5f) * (float)RES);
        int vz = (int)floorf((bzf * 0.5f + 0.5f) * (float)RES);

        idx[i] = bidx * (RES * RES * RES) + vx * (RES * RES) + vy * RES + vz;
    }

    // Phase 2: 2 independent predicated gathers (L2 only; L1 hit rate ~0)
    float r0 = valid[0] ? __ldcg(&occ[idx[0]]) : 0.0f;
    float r1 = valid[1] ? __ldcg(&occ[idx[1]]) : 0.0f;

    float2 o; o.x = r0; o.y = r1;
    __stcs(&out2[t], o);
}

extern "C" void kernel_launch(void* const* d_in, const int* in_sizes, int n_in,
                              void* d_out, int out_size)
{
    const float2* pts2 = (const float2*)d_in[0];
    const float*  occ  = (const float*)d_in[1];
    const int*    lut  = (const int*)d_in[2];
    float2*       out  = (float2*)d_out;

    int n_pts = in_sizes[0] / 3;       // 4,194,304
    int n2    = n_pts / 2;             // 2,097,152

    int threads = 256;
    int blocks  = (n2 + threads - 1) / threads;   // 8192
    occ_forest_kernel<<<blocks, threads>>>(pts2, occ, lut, out, n2);
}